// round 2
// baseline (speedup 1.0000x reference)
#include <cuda_runtime.h>
#include <cstdint>

// Problem constants (fixed shapes per reference)
#define NN 100000
#define DIN 128
#define DH 64
// D_OUT == 64 == DH

// ---------------- scratch (no allocations allowed) ----------------
__device__ float g_dinv[NN];            // deg -> dinv (in place)
__device__ float g_Xl [NN * DH];        // scaled transformed features (gather source)
__device__ float g_agg[NN * DH];        // aggregation buffer (scatter target)
__device__ float g_H  [NN * DH];        // hidden activations

// ---------------- degree / dinv ----------------
__global__ void k_fill_one(int n) {
    int i = blockIdx.x * blockDim.x + threadIdx.x;
    if (i < n) g_dinv[i] = 1.0f;   // self-loop contributes 1 to every degree
}

__global__ void k_deg(const int* __restrict__ dst, int nE) {
    int e = blockIdx.x * blockDim.x + threadIdx.x;
    if (e < nE) atomicAdd(&g_dinv[dst[e]], 1.0f);
}

__global__ void k_rsqrt(int n) {
    int i = blockIdx.x * blockDim.x + threadIdx.x;
    if (i < n) g_dinv[i] = rsqrtf(g_dinv[i]);
}

// ---------------- dense transform: Xl_scaled[i,:] = (X[i,:] @ W) * dinv[i] ----------------
// Also initializes the aggregation buffer with the same value (self-loop term).
template <int K>
__global__ void k_gemm_scale(const float* __restrict__ X, const float* __restrict__ W,
                             int n) {
    __shared__ float sW[K * DH];
    __shared__ float sX[16][K + 1];
    const int tid = threadIdx.x;            // 256 threads
    const int node0 = blockIdx.x * 16;

    for (int i = tid; i < K * DH; i += 256) sW[i] = W[i];
    for (int i = tid; i < 16 * K; i += 256) {
        int r = i / K, c = i - r * K;
        int node = node0 + r;
        sX[r][c] = (node < n) ? X[(size_t)node * K + c] : 0.0f;
    }
    __syncthreads();

    const int r  = tid >> 4;          // local node 0..15
    const int c4 = (tid & 15) * 4;    // output column base
    float4 acc = make_float4(0.f, 0.f, 0.f, 0.f);
#pragma unroll 8
    for (int k = 0; k < K; k++) {
        float xv  = sX[r][k];
        float4 w  = *reinterpret_cast<const float4*>(&sW[k * DH + c4]);
        acc.x += xv * w.x; acc.y += xv * w.y;
        acc.z += xv * w.z; acc.w += xv * w.w;
    }
    const int node = node0 + r;
    if (node < n) {
        float dv = g_dinv[node];
        acc.x *= dv; acc.y *= dv; acc.z *= dv; acc.w *= dv;
        size_t off = (size_t)node * DH + c4;
        *reinterpret_cast<float4*>(&g_Xl [off]) = acc;
        *reinterpret_cast<float4*>(&g_agg[off]) = acc;   // self-loop init
    }
}

// ---------------- edge aggregation: agg[dst] += Xl_scaled[src] ----------------
// Half-warp (16 lanes) per edge: 16 x float4 = 64 floats, coalesced 256B
// gather + vector reduction (red.global.add.v4.f32, no return value).
__global__ void k_edge_agg(const int* __restrict__ src, const int* __restrict__ dst, int nE) {
    int t = blockIdx.x * blockDim.x + threadIdx.x;
    int e = t >> 4;
    if (e >= nE) return;
    int lane = t & 15;
    int s = __ldg(src + e);
    int d = __ldg(dst + e);
    float4 v = *reinterpret_cast<const float4*>(g_Xl + (size_t)s * DH + lane * 4);
    float* addr = g_agg + (size_t)d * DH + lane * 4;
    asm volatile("red.global.add.v4.f32 [%0], {%1, %2, %3, %4};"
                 :: "l"(addr), "f"(v.x), "f"(v.y), "f"(v.z), "f"(v.w)
                 : "memory");
}

// ---------------- epilogues ----------------
// H[i,c] = relu(agg[i,c] * dinv[i] + b1[c])
__global__ void k_final_relu(const float* __restrict__ b, int n) {
    int t = blockIdx.x * blockDim.x + threadIdx.x;
    if (t >= n * 16) return;
    int node = t >> 4;
    int c4 = (t & 15) * 4;
    float dv = g_dinv[node];
    size_t off = (size_t)node * DH + c4;
    float4 a  = *reinterpret_cast<const float4*>(g_agg + off);
    float4 bb = *reinterpret_cast<const float4*>(b + c4);
    float4 h;
    h.x = fmaxf(a.x * dv + bb.x, 0.f);
    h.y = fmaxf(a.y * dv + bb.y, 0.f);
    h.z = fmaxf(a.z * dv + bb.z, 0.f);
    h.w = fmaxf(a.w * dv + bb.w, 0.f);
    *reinterpret_cast<float4*>(g_H + off) = h;
}

// out[i,c] = agg[i,c] * dinv[i] + b2[c]   (no relu)
__global__ void k_final_out(const float* __restrict__ b, float* __restrict__ out, int n) {
    int t = blockIdx.x * blockDim.x + threadIdx.x;
    if (t >= n * 16) return;
    int node = t >> 4;
    int c4 = (t & 15) * 4;
    float dv = g_dinv[node];
    size_t off = (size_t)node * DH + c4;
    float4 a  = *reinterpret_cast<const float4*>(g_agg + off);
    float4 bb = *reinterpret_cast<const float4*>(b + c4);
    float4 o;
    o.x = a.x * dv + bb.x;
    o.y = a.y * dv + bb.y;
    o.z = a.z * dv + bb.z;
    o.w = a.w * dv + bb.w;
    *reinterpret_cast<float4*>(out + off) = o;
}

// ---------------- host launch ----------------
extern "C" void kernel_launch(void* const* d_in, const int* in_sizes, int n_in,
                              void* d_out, int out_size) {
    // Identify inputs by size (robust to scalar-V presence/ordering):
    //   E: 2*1.6M ints, X: 100k*128, W1: 128*64, W2: 64*64, b1/b2: 64 each (in order)
    const int*   E  = nullptr;
    const float* X  = nullptr;
    const float* W1 = nullptr;
    const float* b1 = nullptr;
    const float* W2 = nullptr;
    const float* b2 = nullptr;
    long nE_total = 0;
    for (int i = 0; i < n_in; i++) {
        long sz = in_sizes[i];
        if (sz == 2L * 1600000)      { E = (const int*)d_in[i]; nE_total = sz / 2; }
        else if (sz == (long)NN * DIN) X  = (const float*)d_in[i];
        else if (sz == DIN * DH)       W1 = (const float*)d_in[i];
        else if (sz == DH * DH)        W2 = (const float*)d_in[i];
        else if (sz == DH)             { if (!b1) b1 = (const float*)d_in[i];
                                         else     b2 = (const float*)d_in[i]; }
    }
    const int n  = NN;
    const int nE = (int)nE_total;
    const int* src = E;          // E[0]
    const int* dst = E + nE;     // E[1]
    float* out = (float*)d_out;

    // Device address of g_H (a __device__ symbol CANNOT be passed to a kernel
    // by naming it in host code — that was the round-1 bug).
    void* hptr = nullptr;
    cudaGetSymbolAddress(&hptr, g_H);
    const float* Hdev = (const float*)hptr;

    const int T = 256;
    dim3 blkNode((n + T - 1) / T);
    dim3 blkEdge((nE + T - 1) / T);
    dim3 blkGemm((n + 15) / 16);
    dim3 blkEdgeV(((long)nE * 16 + T - 1) / T);
    dim3 blkElem(((long)n * 16 + T - 1) / T);

    // degree -> dinv (self-loop included via init = 1)
    k_fill_one<<<blkNode, T>>>(n);
    k_deg<<<blkEdge, T>>>(dst, nE);
    k_rsqrt<<<blkNode, T>>>(n);

    // layer 1
    k_gemm_scale<DIN><<<blkGemm, T>>>(X, W1, n);
    k_edge_agg<<<blkEdgeV, T>>>(src, dst, nE);
    k_final_relu<<<blkElem, T>>>(b1, n);

    // layer 2
    k_gemm_scale<DH><<<blkGemm, T>>>(Hdev, W2, n);
    k_edge_agg<<<blkEdgeV, T>>>(src, dst, nE);
    k_final_out<<<blkElem, T>>>(b2, out, n);
}

// round 3
// speedup vs baseline: 1.4764x; 1.4764x over previous
#include <cuda_runtime.h>
#include <cstdint>

// Problem constants (fixed shapes per reference)
#define NN 100000
#define DIN 128
#define DH 64
// D_OUT == 64 == DH

// ---------------- scratch (no allocations allowed) ----------------
__device__ float g_dinv[NN];            // deg -> dinv (in place)
__device__ float g_Xl [NN * DH];        // scaled transformed features (gather source)
__device__ float g_agg[NN * DH];        // aggregation buffer (scatter target)

// ---------------- degree / dinv ----------------
__global__ void k_fill_one(int n) {
    int i = blockIdx.x * blockDim.x + threadIdx.x;
    if (i < n) g_dinv[i] = 1.0f;   // self-loop contributes 1 to every degree
}

__global__ void k_deg(const int* __restrict__ dst, int nE) {
    int e = blockIdx.x * blockDim.x + threadIdx.x;
    if (e < nE) atomicAdd(&g_dinv[dst[e]], 1.0f);
}

__global__ void k_rsqrt(int n) {
    int i = blockIdx.x * blockDim.x + threadIdx.x;
    if (i < n) g_dinv[i] = rsqrtf(g_dinv[i]);
}

// ---------------- register-blocked GEMM + scale ----------------
// Xl_scaled[i,:] = (act(X[i,:]) @ W) * dinv[i] ; also inits g_agg (self-loop).
// Tile: 128 nodes x 64 cols per block (256 threads), 4 nodes x 8 cols per thread.
// If FUSE: input rows are act = relu(X[i,k]*dinv[i] + bias[k])  (layer-2 path,
// where X points at g_agg from layer 1).
template <int K, bool FUSE>
__global__ __launch_bounds__(256) void k_gemm_scale(const float* __restrict__ X,
                                                    const float* __restrict__ W,
                                                    const float* __restrict__ bias,
                                                    int n) {
    __shared__ float sX[128 * 20];   // [row][k] stride 20 (16B-aligned rows)
    __shared__ float sW[16 * 64];    // [k][col]

    const int node0 = blockIdx.x * 128;
    const int tid = threadIdx.x;
    const int tr = tid >> 3;         // 0..31  -> node group (4 nodes)
    const int tc = tid & 7;          // 0..7   -> col group (8 cols)

    float acc[4][8];
#pragma unroll
    for (int i = 0; i < 4; i++)
#pragma unroll
        for (int j = 0; j < 8; j++) acc[i][j] = 0.f;

    for (int k0 = 0; k0 < K; k0 += 16) {
        // --- load X tile: 128 rows x 16 k, 2 float4 per thread ---
#pragma unroll
        for (int t = 0; t < 2; t++) {
            int u = tid + t * 256;           // 0..511
            int row = u >> 2;
            int c4 = (u & 3) * 4;
            int node = node0 + row;
            float4 v = make_float4(0.f, 0.f, 0.f, 0.f);
            if (node < n) {
                v = *reinterpret_cast<const float4*>(X + (size_t)node * K + k0 + c4);
                if (FUSE) {
                    float dv = g_dinv[node];
                    float4 bb = *reinterpret_cast<const float4*>(bias + k0 + c4);
                    v.x = fmaxf(fmaf(v.x, dv, bb.x), 0.f);
                    v.y = fmaxf(fmaf(v.y, dv, bb.y), 0.f);
                    v.z = fmaxf(fmaf(v.z, dv, bb.z), 0.f);
                    v.w = fmaxf(fmaf(v.w, dv, bb.w), 0.f);
                }
            }
            *reinterpret_cast<float4*>(sX + row * 20 + c4) = v;
        }
        // --- load W tile: 16 k x 64 cols, 1 float4 per thread ---
        {
            int kk = tid >> 4;               // 0..15
            int c4 = (tid & 15) * 4;
            *reinterpret_cast<float4*>(sW + kk * 64 + c4) =
                *reinterpret_cast<const float4*>(W + (size_t)(k0 + kk) * 64 + c4);
        }
        __syncthreads();

#pragma unroll
        for (int k = 0; k < 16; k++) {
            float4 w0 = *reinterpret_cast<const float4*>(sW + k * 64 + tc * 8);
            float4 w1 = *reinterpret_cast<const float4*>(sW + k * 64 + tc * 8 + 4);
#pragma unroll
            for (int i = 0; i < 4; i++) {
                float x = sX[(tr * 4 + i) * 20 + k];
                acc[i][0] += x * w0.x; acc[i][1] += x * w0.y;
                acc[i][2] += x * w0.z; acc[i][3] += x * w0.w;
                acc[i][4] += x * w1.x; acc[i][5] += x * w1.y;
                acc[i][6] += x * w1.z; acc[i][7] += x * w1.w;
            }
        }
        __syncthreads();
    }

    // --- epilogue: scale by dinv, write g_Xl and g_agg (self-loop init) ---
#pragma unroll
    for (int i = 0; i < 4; i++) {
        int node = node0 + tr * 4 + i;
        if (node < n) {
            float dv = g_dinv[node];
            float4 a0 = make_float4(acc[i][0] * dv, acc[i][1] * dv,
                                    acc[i][2] * dv, acc[i][3] * dv);
            float4 a1 = make_float4(acc[i][4] * dv, acc[i][5] * dv,
                                    acc[i][6] * dv, acc[i][7] * dv);
            size_t off = (size_t)node * DH + tc * 8;
            *reinterpret_cast<float4*>(g_Xl + off)     = a0;
            *reinterpret_cast<float4*>(g_Xl + off + 4) = a1;
            *reinterpret_cast<float4*>(g_agg + off)     = a0;
            *reinterpret_cast<float4*>(g_agg + off + 4) = a1;
        }
    }
}

// ---------------- edge aggregation: agg[dst] += Xl_scaled[src] ----------------
// Half-warp (16 lanes) per edge: 16 x float4 = 64 floats, coalesced 256B
// gather + vector reduction (red.global.add.v4.f32, no return value).
__global__ void k_edge_agg(const int* __restrict__ src, const int* __restrict__ dst, int nE) {
    int t = blockIdx.x * blockDim.x + threadIdx.x;
    int e = t >> 4;
    if (e >= nE) return;
    int lane = t & 15;
    int s = __ldg(src + e);
    int d = __ldg(dst + e);
    float4 v = *reinterpret_cast<const float4*>(g_Xl + (size_t)s * DH + lane * 4);
    float* addr = g_agg + (size_t)d * DH + lane * 4;
    asm volatile("red.global.add.v4.f32 [%0], {%1, %2, %3, %4};"
                 :: "l"(addr), "f"(v.x), "f"(v.y), "f"(v.z), "f"(v.w)
                 : "memory");
}

// out[i,c] = agg[i,c] * dinv[i] + b2[c]   (no relu)
__global__ void k_final_out(const float* __restrict__ b, float* __restrict__ out, int n) {
    int t = blockIdx.x * blockDim.x + threadIdx.x;
    if (t >= n * 16) return;
    int node = t >> 4;
    int c4 = (t & 15) * 4;
    float dv = g_dinv[node];
    size_t off = (size_t)node * DH + c4;
    float4 a  = *reinterpret_cast<const float4*>(g_agg + off);
    float4 bb = *reinterpret_cast<const float4*>(b + c4);
    float4 o;
    o.x = a.x * dv + bb.x;
    o.y = a.y * dv + bb.y;
    o.z = a.z * dv + bb.z;
    o.w = a.w * dv + bb.w;
    *reinterpret_cast<float4*>(out + off) = o;
}

// ---------------- host launch ----------------
extern "C" void kernel_launch(void* const* d_in, const int* in_sizes, int n_in,
                              void* d_out, int out_size) {
    const int*   E  = nullptr;
    const float* X  = nullptr;
    const float* W1 = nullptr;
    const float* b1 = nullptr;
    const float* W2 = nullptr;
    const float* b2 = nullptr;
    long nE_total = 0;
    for (int i = 0; i < n_in; i++) {
        long sz = in_sizes[i];
        if (sz == 2L * 1600000)      { E = (const int*)d_in[i]; nE_total = sz / 2; }
        else if (sz == (long)NN * DIN) X  = (const float*)d_in[i];
        else if (sz == DIN * DH)       W1 = (const float*)d_in[i];
        else if (sz == DH * DH)        W2 = (const float*)d_in[i];
        else if (sz == DH)             { if (!b1) b1 = (const float*)d_in[i];
                                         else     b2 = (const float*)d_in[i]; }
    }
    const int n  = NN;
    const int nE = (int)nE_total;
    const int* src = E;          // E[0]
    const int* dst = E + nE;     // E[1]
    float* out = (float*)d_out;

    // Device addresses of __device__ symbols (cannot be named from host code
    // as kernel args directly — round-1 lesson).
    void* aptr = nullptr;
    cudaGetSymbolAddress(&aptr, g_agg);
    const float* AGGdev = (const float*)aptr;

    const int T = 256;
    dim3 blkNode((n + T - 1) / T);
    dim3 blkEdge((nE + T - 1) / T);
    dim3 blkGemm((n + 127) / 128);
    dim3 blkEdgeV(((long)nE * 16 + T - 1) / T);
    dim3 blkElem(((long)n * 16 + T - 1) / T);

    // degree -> dinv (self-loop included via init = 1)
    k_fill_one<<<blkNode, T>>>(n);
    k_deg<<<blkEdge, T>>>(dst, nE);
    k_rsqrt<<<blkNode, T>>>(n);

    // layer 1: Xl = (X @ W1) * dinv ; agg := Xl (self loop)
    k_gemm_scale<DIN, false><<<blkGemm, T>>>(X, W1, nullptr, n);
    k_edge_agg<<<blkEdgeV, T>>>(src, dst, nE);

    // layer 2: input rows H = relu(agg*dinv + b1) computed on the fly (FUSE)
    k_gemm_scale<DH, true><<<blkGemm, T>>>(AGGdev, W2, b1, n);
    k_edge_agg<<<blkEdgeV, T>>>(src, dst, nE);
    k_final_out<<<blkElem, T>>>(b2, out, n);
}

// round 4
// speedup vs baseline: 1.9873x; 1.3460x over previous
#include <cuda_runtime.h>
#include <cstdint>

// Problem constants (fixed shapes per reference)
#define NN 100000
#define NE 1600000
#define DIN 128
#define DH 64
#define NB_SCAN ((NN + 1023) / 1024)   // 98

// ---------------- scratch (no allocations allowed) ----------------
__device__ float g_dinv[NN];           // rsqrt(deg)
__device__ int   g_cnt[NN];            // in-degree histogram (excl. self loop)
__device__ int   g_rowptr[NN];         // CSR row start
__device__ int   g_cursor[NN];         // scatter cursors
__device__ int   g_bsum[NB_SCAN];      // scan partials
__device__ int   g_csr_src[NE];        // CSR column (src) indices
__device__ float g_Xl [NN * DH];       // pre-scaled transformed features (gather source)
__device__ float g_agg[NN * DH];       // H activations (layer-1 output)

// ---------------- CSR build ----------------
__global__ void k_zero_cnt(int n) {
    int i = blockIdx.x * blockDim.x + threadIdx.x;
    if (i < n) g_cnt[i] = 0;
}

__global__ void k_hist(const int* __restrict__ dst, int nE) {
    int e = blockIdx.x * blockDim.x + threadIdx.x;
    if (e < nE) atomicAdd(&g_cnt[dst[e]], 1);
}

// per-1024-block exclusive scan of g_cnt -> g_rowptr(local) + block sums
__global__ __launch_bounds__(1024) void k_scan1(int n) {
    __shared__ int s[1024];
    int i = blockIdx.x * 1024 + threadIdx.x;
    int v = (i < n) ? g_cnt[i] : 0;
    s[threadIdx.x] = v;
    __syncthreads();
    for (int off = 1; off < 1024; off <<= 1) {
        int t = (threadIdx.x >= off) ? s[threadIdx.x - off] : 0;
        __syncthreads();
        s[threadIdx.x] += t;
        __syncthreads();
    }
    if (i < n) g_rowptr[i] = s[threadIdx.x] - v;       // exclusive
    if (threadIdx.x == 1023) g_bsum[blockIdx.x] = s[1023];
}

// scan of NB_SCAN block sums (single block)
__global__ __launch_bounds__(128) void k_scan2(int nb) {
    __shared__ int s[128];
    int v = (threadIdx.x < nb) ? g_bsum[threadIdx.x] : 0;
    s[threadIdx.x] = v;
    __syncthreads();
    for (int off = 1; off < 128; off <<= 1) {
        int t = (threadIdx.x >= off) ? s[threadIdx.x - off] : 0;
        __syncthreads();
        s[threadIdx.x] += t;
        __syncthreads();
    }
    if (threadIdx.x < nb) g_bsum[threadIdx.x] = s[threadIdx.x] - v;  // exclusive
}

// add block offsets; init cursors; compute dinv = rsqrt(deg+1) (self loop)
__global__ void k_scan3(int n) {
    int i = blockIdx.x * blockDim.x + threadIdx.x;
    if (i >= n) return;
    int rp = g_rowptr[i] + g_bsum[i >> 10];
    g_rowptr[i] = rp;
    g_cursor[i] = rp;
    g_dinv[i] = rsqrtf((float)g_cnt[i] + 1.0f);
}

__global__ void k_scatter(const int* __restrict__ src, const int* __restrict__ dst, int nE) {
    int e = blockIdx.x * blockDim.x + threadIdx.x;
    if (e >= nE) return;
    int d = dst[e];
    int pos = atomicAdd(&g_cursor[d], 1);
    g_csr_src[pos] = src[e];
}

// ---------------- register-blocked GEMM + scale ----------------
// g_Xl[i,:] = (X[i,:] @ W) * dinv[i]
// Tile: 128 nodes x 64 cols per block (256 threads), 4 nodes x 8 cols per thread.
template <int K>
__global__ __launch_bounds__(256) void k_gemm_scale(const float* __restrict__ X,
                                                    const float* __restrict__ W,
                                                    int n) {
    __shared__ float sX[128 * 20];   // [row][k] stride 20 (16B-aligned rows)
    __shared__ float sW[16 * 64];    // [k][col]

    const int node0 = blockIdx.x * 128;
    const int tid = threadIdx.x;
    const int tr = tid >> 3;         // 0..31  -> node group (4 nodes)
    const int tc = tid & 7;          // 0..7   -> col group (8 cols)

    float acc[4][8];
#pragma unroll
    for (int i = 0; i < 4; i++)
#pragma unroll
        for (int j = 0; j < 8; j++) acc[i][j] = 0.f;

    for (int k0 = 0; k0 < K; k0 += 16) {
#pragma unroll
        for (int t = 0; t < 2; t++) {
            int u = tid + t * 256;           // 0..511
            int row = u >> 2;
            int c4 = (u & 3) * 4;
            int node = node0 + row;
            float4 v = make_float4(0.f, 0.f, 0.f, 0.f);
            if (node < n)
                v = *reinterpret_cast<const float4*>(X + (size_t)node * K + k0 + c4);
            *reinterpret_cast<float4*>(sX + row * 20 + c4) = v;
        }
        {
            int kk = tid >> 4;               // 0..15
            int c4 = (tid & 15) * 4;
            *reinterpret_cast<float4*>(sW + kk * 64 + c4) =
                *reinterpret_cast<const float4*>(W + (size_t)(k0 + kk) * 64 + c4);
        }
        __syncthreads();

#pragma unroll
        for (int k = 0; k < 16; k++) {
            float4 w0 = *reinterpret_cast<const float4*>(sW + k * 64 + tc * 8);
            float4 w1 = *reinterpret_cast<const float4*>(sW + k * 64 + tc * 8 + 4);
#pragma unroll
            for (int i = 0; i < 4; i++) {
                float x = sX[(tr * 4 + i) * 20 + k];
                acc[i][0] += x * w0.x; acc[i][1] += x * w0.y;
                acc[i][2] += x * w0.z; acc[i][3] += x * w0.w;
                acc[i][4] += x * w1.x; acc[i][5] += x * w1.y;
                acc[i][6] += x * w1.z; acc[i][7] += x * w1.w;
            }
        }
        __syncthreads();
    }

#pragma unroll
    for (int i = 0; i < 4; i++) {
        int node = node0 + tr * 4 + i;
        if (node < n) {
            float dv = g_dinv[node];
            float4 a0 = make_float4(acc[i][0] * dv, acc[i][1] * dv,
                                    acc[i][2] * dv, acc[i][3] * dv);
            float4 a1 = make_float4(acc[i][4] * dv, acc[i][5] * dv,
                                    acc[i][6] * dv, acc[i][7] * dv);
            size_t off = (size_t)node * DH + tc * 8;
            *reinterpret_cast<float4*>(g_Xl + off)     = a0;
            *reinterpret_cast<float4*>(g_Xl + off + 4) = a1;
        }
    }
}

// ---------------- CSR gather aggregation (no atomics) ----------------
// One warp per node; lane owns 2 columns (float2).
//   acc = Xl[node] (self loop) + sum_{s in CSR row} Xl[s]
//   MODE 0: g_agg[node] = relu(acc * dinv + b)      (layer 1 -> H)
//   MODE 1: out[node]   = acc * dinv + b            (layer 2 -> output)
template <int MODE>
__global__ __launch_bounds__(256) void k_gather(const float* __restrict__ bias,
                                                float* __restrict__ outbuf, int n) {
    int gw = (blockIdx.x * blockDim.x + threadIdx.x) >> 5;
    if (gw >= n) return;
    const int lane = threadIdx.x & 31;
    const int start = g_rowptr[gw];
    const int cnt   = g_cnt[gw];

    const float* rowSelf = g_Xl + (size_t)gw * DH + lane * 2;
    float2 acc = *reinterpret_cast<const float2*>(rowSelf);   // self loop

    for (int j0 = 0; j0 < cnt; j0 += 32) {
        int m = cnt - j0; if (m > 32) m = 32;
        int myidx = (lane < m) ? g_csr_src[start + j0 + lane] : 0;
        for (int t = 0; t < m; t++) {
            int s = __shfl_sync(0xffffffffu, myidx, t);
            float2 v = *reinterpret_cast<const float2*>(g_Xl + (size_t)s * DH + lane * 2);
            acc.x += v.x; acc.y += v.y;
        }
    }

    float dv = g_dinv[gw];
    float2 bb = *reinterpret_cast<const float2*>(bias + lane * 2);
    float2 o;
    o.x = fmaf(acc.x, dv, bb.x);
    o.y = fmaf(acc.y, dv, bb.y);
    if (MODE == 0) { o.x = fmaxf(o.x, 0.f); o.y = fmaxf(o.y, 0.f); }
    float* dstp = (MODE == 0) ? (g_agg + (size_t)gw * DH + lane * 2)
                              : (outbuf + (size_t)gw * DH + lane * 2);
    *reinterpret_cast<float2*>(dstp) = o;
}

// ---------------- host launch ----------------
extern "C" void kernel_launch(void* const* d_in, const int* in_sizes, int n_in,
                              void* d_out, int out_size) {
    const int*   E  = nullptr;
    const float* X  = nullptr;
    const float* W1 = nullptr;
    const float* b1 = nullptr;
    const float* W2 = nullptr;
    const float* b2 = nullptr;
    long nE_total = 0;
    for (int i = 0; i < n_in; i++) {
        long sz = in_sizes[i];
        if (sz == 2L * NE)           { E = (const int*)d_in[i]; nE_total = sz / 2; }
        else if (sz == (long)NN * DIN) X  = (const float*)d_in[i];
        else if (sz == DIN * DH)       W1 = (const float*)d_in[i];
        else if (sz == DH * DH)        W2 = (const float*)d_in[i];
        else if (sz == DH)             { if (!b1) b1 = (const float*)d_in[i];
                                         else     b2 = (const float*)d_in[i]; }
    }
    const int n  = NN;
    const int nE = (int)nE_total;
    const int* src = E;          // E[0]
    const int* dst = E + nE;     // E[1]
    float* out = (float*)d_out;

    // Device address of g_agg (device symbols can't be named from host as
    // kernel args — round-1 lesson).
    void* aptr = nullptr;
    cudaGetSymbolAddress(&aptr, g_agg);
    const float* Hdev = (const float*)aptr;

    const int T = 256;
    dim3 blkNode((n + T - 1) / T);
    dim3 blkEdge((nE + T - 1) / T);
    dim3 blkGemm((n + 127) / 128);
    dim3 blkWarp(((long)n * 32 + T - 1) / T);

    // ---- CSR build (also produces dinv) ----
    k_zero_cnt<<<blkNode, T>>>(n);
    k_hist<<<blkEdge, T>>>(dst, nE);
    k_scan1<<<NB_SCAN, 1024>>>(n);
    k_scan2<<<1, 128>>>(NB_SCAN);
    k_scan3<<<blkNode, T>>>(n);
    k_scatter<<<blkEdge, T>>>(src, dst, nE);

    // ---- layer 1: Xl = (X @ W1) * dinv ; H = relu(gather * dinv + b1) ----
    k_gemm_scale<DIN><<<blkGemm, T>>>(X, W1, n);
    k_gather<0><<<blkWarp, T>>>(b1, nullptr, n);

    // ---- layer 2: Xl = (H @ W2) * dinv ; out = gather * dinv + b2 ----
    k_gemm_scale<DH><<<blkGemm, T>>>(Hdev, W2, n);
    k_gather<1><<<blkWarp, T>>>(b2, out, n);
}

// round 5
// speedup vs baseline: 2.0273x; 1.0201x over previous
#include <cuda_runtime.h>
#include <cstdint>

// Problem constants (fixed shapes per reference)
#define NN 100000
#define NE 1600000
#define DIN 128
#define DH 64
#define NB_SCAN ((NN + 1023) / 1024)   // 98

// ---------------- scratch (no allocations allowed) ----------------
__device__ float g_dinv[NN];           // rsqrt(deg+1)
__device__ int   g_cnt[NN];            // in-degree histogram (excl. self loop)
__device__ int   g_rowptr[NN];         // CSR row start
__device__ int   g_cursor[NN];         // scatter cursors
__device__ int   g_bsum[NB_SCAN];      // scan partials
__device__ int   g_csr_src[NE];        // CSR column (src) indices
__device__ float g_Xl [NN * DH];       // RAW transformed features (gather source)
__device__ float g_agg[NN * DH];       // H activations (layer-1 output)

// ---------------- CSR build ----------------
__global__ void k_zero_cnt(int n) {
    int i = blockIdx.x * blockDim.x + threadIdx.x;
    if (i < n) g_cnt[i] = 0;
}

__global__ void k_hist(const int* __restrict__ dst, int nE) {
    int e = blockIdx.x * blockDim.x + threadIdx.x;
    if (e < nE) atomicAdd(&g_cnt[dst[e]], 1);
}

// per-1024-block exclusive scan of g_cnt -> g_rowptr(local) + block sums
__global__ __launch_bounds__(1024) void k_scan1(int n) {
    __shared__ int s[1024];
    int i = blockIdx.x * 1024 + threadIdx.x;
    int v = (i < n) ? g_cnt[i] : 0;
    s[threadIdx.x] = v;
    __syncthreads();
    for (int off = 1; off < 1024; off <<= 1) {
        int t = (threadIdx.x >= off) ? s[threadIdx.x - off] : 0;
        __syncthreads();
        s[threadIdx.x] += t;
        __syncthreads();
    }
    if (i < n) g_rowptr[i] = s[threadIdx.x] - v;       // exclusive
    if (threadIdx.x == 1023) g_bsum[blockIdx.x] = s[1023];
}

// scan of NB_SCAN block sums (single block)
__global__ __launch_bounds__(128) void k_scan2(int nb) {
    __shared__ int s[128];
    int v = (threadIdx.x < nb) ? g_bsum[threadIdx.x] : 0;
    s[threadIdx.x] = v;
    __syncthreads();
    for (int off = 1; off < 128; off <<= 1) {
        int t = (threadIdx.x >= off) ? s[threadIdx.x - off] : 0;
        __syncthreads();
        s[threadIdx.x] += t;
        __syncthreads();
    }
    if (threadIdx.x < nb) g_bsum[threadIdx.x] = s[threadIdx.x] - v;  // exclusive
}

// add block offsets; init cursors; compute dinv = rsqrt(deg+1) (self loop)
__global__ void k_scan3(int n) {
    int i = blockIdx.x * blockDim.x + threadIdx.x;
    if (i >= n) return;
    int rp = g_rowptr[i] + g_bsum[i >> 10];
    g_rowptr[i] = rp;
    g_cursor[i] = rp;
    g_dinv[i] = rsqrtf((float)g_cnt[i] + 1.0f);
}

__global__ void k_scatter(const int* __restrict__ src, const int* __restrict__ dst, int nE) {
    int e = blockIdx.x * blockDim.x + threadIdx.x;
    if (e >= nE) return;
    int d = dst[e];
    int pos = atomicAdd(&g_cursor[d], 1);
    g_csr_src[pos] = src[e];
}

// ---------------- register-blocked GEMM (raw, no dinv) ----------------
// g_Xl[i,:] = X[i,:] @ W
// Tile: 128 nodes x 64 cols per block (256 threads), 4 nodes x 8 cols per thread.
template <int K>
__global__ __launch_bounds__(256) void k_gemm(const float* __restrict__ X,
                                              const float* __restrict__ W,
                                              int n) {
    __shared__ float sX[128 * 20];   // [row][k] stride 20 (16B-aligned rows)
    __shared__ float sW[16 * 64];    // [k][col]

    const int node0 = blockIdx.x * 128;
    const int tid = threadIdx.x;
    const int tr = tid >> 3;         // 0..31  -> node group (4 nodes)
    const int tc = tid & 7;          // 0..7   -> col group (8 cols)

    float acc[4][8];
#pragma unroll
    for (int i = 0; i < 4; i++)
#pragma unroll
        for (int j = 0; j < 8; j++) acc[i][j] = 0.f;

    for (int k0 = 0; k0 < K; k0 += 16) {
#pragma unroll
        for (int t = 0; t < 2; t++) {
            int u = tid + t * 256;           // 0..511
            int row = u >> 2;
            int c4 = (u & 3) * 4;
            int node = node0 + row;
            float4 v = make_float4(0.f, 0.f, 0.f, 0.f);
            if (node < n)
                v = *reinterpret_cast<const float4*>(X + (size_t)node * K + k0 + c4);
            *reinterpret_cast<float4*>(sX + row * 20 + c4) = v;
        }
        {
            int kk = tid >> 4;               // 0..15
            int c4 = (tid & 15) * 4;
            *reinterpret_cast<float4*>(sW + kk * 64 + c4) =
                *reinterpret_cast<const float4*>(W + (size_t)(k0 + kk) * 64 + c4);
        }
        __syncthreads();

#pragma unroll
        for (int k = 0; k < 16; k++) {
            float4 w0 = *reinterpret_cast<const float4*>(sW + k * 64 + tc * 8);
            float4 w1 = *reinterpret_cast<const float4*>(sW + k * 64 + tc * 8 + 4);
#pragma unroll
            for (int i = 0; i < 4; i++) {
                float x = sX[(tr * 4 + i) * 20 + k];
                acc[i][0] += x * w0.x; acc[i][1] += x * w0.y;
                acc[i][2] += x * w0.z; acc[i][3] += x * w0.w;
                acc[i][4] += x * w1.x; acc[i][5] += x * w1.y;
                acc[i][6] += x * w1.z; acc[i][7] += x * w1.w;
            }
        }
        __syncthreads();
    }

#pragma unroll
    for (int i = 0; i < 4; i++) {
        int node = node0 + tr * 4 + i;
        if (node < n) {
            size_t off = (size_t)node * DH + tc * 8;
            *reinterpret_cast<float4*>(g_Xl + off) =
                make_float4(acc[i][0], acc[i][1], acc[i][2], acc[i][3]);
            *reinterpret_cast<float4*>(g_Xl + off + 4) =
                make_float4(acc[i][4], acc[i][5], acc[i][6], acc[i][7]);
        }
    }
}

// ---------------- CSR gather aggregation (no atomics) ----------------
// One warp per node; lane owns 2 columns (float2).
//   acc = dinv[node]*Xl[node] (self loop) + sum_{s in row} dinv[s]*Xl[s]
//   MODE 0: g_agg[node] = relu(acc * dinv + b)      (layer 1 -> H)
//   MODE 1: out[node]   = acc * dinv + b            (layer 2 -> output)
template <int MODE>
__global__ __launch_bounds__(256) void k_gather(const float* __restrict__ bias,
                                                float* __restrict__ outbuf, int n) {
    int gw = (blockIdx.x * blockDim.x + threadIdx.x) >> 5;
    if (gw >= n) return;
    const int lane = threadIdx.x & 31;
    const int start = g_rowptr[gw];
    const int cnt   = g_cnt[gw];
    const float dvd = g_dinv[gw];

    float2 self = *reinterpret_cast<const float2*>(g_Xl + (size_t)gw * DH + lane * 2);
    float2 acc = make_float2(self.x * dvd, self.y * dvd);   // self loop (dinv_self)

    for (int j0 = 0; j0 < cnt; j0 += 32) {
        int m = cnt - j0; if (m > 32) m = 32;
        int myidx = 0; float myd = 0.f;
        if (lane < m) {
            myidx = g_csr_src[start + j0 + lane];
            myd   = g_dinv[myidx];
        }
        for (int t = 0; t < m; t++) {
            int   s = __shfl_sync(0xffffffffu, myidx, t);
            float d = __shfl_sync(0xffffffffu, myd,   t);
            float2 v = *reinterpret_cast<const float2*>(g_Xl + (size_t)s * DH + lane * 2);
            acc.x = fmaf(d, v.x, acc.x);
            acc.y = fmaf(d, v.y, acc.y);
        }
    }

    float2 bb = *reinterpret_cast<const float2*>(bias + lane * 2);
    float2 o;
    o.x = fmaf(acc.x, dvd, bb.x);
    o.y = fmaf(acc.y, dvd, bb.y);
    if (MODE == 0) { o.x = fmaxf(o.x, 0.f); o.y = fmaxf(o.y, 0.f); }
    float* dstp = (MODE == 0) ? (g_agg + (size_t)gw * DH + lane * 2)
                              : (outbuf + (size_t)gw * DH + lane * 2);
    *reinterpret_cast<float2*>(dstp) = o;
}

// ---------------- host launch ----------------
extern "C" void kernel_launch(void* const* d_in, const int* in_sizes, int n_in,
                              void* d_out, int out_size) {
    const int*   E  = nullptr;
    const float* X  = nullptr;
    const float* W1 = nullptr;
    const float* b1 = nullptr;
    const float* W2 = nullptr;
    const float* b2 = nullptr;
    long nE_total = 0;
    for (int i = 0; i < n_in; i++) {
        long sz = in_sizes[i];
        if (sz == 2L * NE)           { E = (const int*)d_in[i]; nE_total = sz / 2; }
        else if (sz == (long)NN * DIN) X  = (const float*)d_in[i];
        else if (sz == DIN * DH)       W1 = (const float*)d_in[i];
        else if (sz == DH * DH)        W2 = (const float*)d_in[i];
        else if (sz == DH)             { if (!b1) b1 = (const float*)d_in[i];
                                         else     b2 = (const float*)d_in[i]; }
    }
    const int n  = NN;
    const int nE = (int)nE_total;
    const int* src = E;          // E[0]
    const int* dst = E + nE;     // E[1]
    float* out = (float*)d_out;

    // Device address of g_agg (device symbols can't be named from host as
    // kernel args — round-1 lesson).
    void* aptr = nullptr;
    cudaGetSymbolAddress(&aptr, g_agg);
    const float* Hdev = (const float*)aptr;

    // One-time side stream + fork/join events (created on the first,
    // uncaptured, correctness call; reused every call — identical work each
    // call, no result caching, no device allocation).
    static cudaStream_t s1 = nullptr;
    static cudaEvent_t  eFork = nullptr, eJoin = nullptr;
    if (s1 == nullptr) {
        cudaStreamCreateWithFlags(&s1, cudaStreamNonBlocking);
        cudaEventCreateWithFlags(&eFork, cudaEventDisableTiming);
        cudaEventCreateWithFlags(&eJoin, cudaEventDisableTiming);
    }

    const int T = 256;
    dim3 blkNode((n + T - 1) / T);
    dim3 blkEdge((nE + T - 1) / T);
    dim3 blkGemm((n + 127) / 128);
    dim3 blkWarp(((long)n * 32 + T - 1) / T);

    // ---- fork: CSR build (+dinv) on s1, concurrent with GEMM1 on main ----
    cudaEventRecord(eFork, 0);
    cudaStreamWaitEvent(s1, eFork, 0);

    k_zero_cnt<<<blkNode, T, 0, s1>>>(n);
    k_hist<<<blkEdge, T, 0, s1>>>(dst, nE);
    k_scan1<<<NB_SCAN, 1024, 0, s1>>>(n);
    k_scan2<<<1, 128, 0, s1>>>(NB_SCAN);
    k_scan3<<<blkNode, T, 0, s1>>>(n);
    k_scatter<<<blkEdge, T, 0, s1>>>(src, dst, nE);
    cudaEventRecord(eJoin, s1);

    // ---- main chain ----
    k_gemm<DIN><<<blkGemm, T>>>(X, W1, n);            // independent of CSR
    cudaStreamWaitEvent(0, eJoin, 0);                 // join before gather

    k_gather<0><<<blkWarp, T>>>(b1, nullptr, n);      // H = relu(...)
    k_gemm<DH><<<blkGemm, T>>>(Hdev, W2, n);
    k_gather<1><<<blkWarp, T>>>(b2, out, n);
}

// round 6
// speedup vs baseline: 2.1178x; 1.0447x over previous
#include <cuda_runtime.h>
#include <cuda_fp16.h>
#include <cstdint>

// Problem constants (fixed shapes per reference)
#define NN 100000
#define NE 1600000
#define DIN 128
#define DH 64
#define NB_SCAN ((NN + 1023) / 1024)   // 98

// ---------------- scratch (no allocations allowed) ----------------
__device__ float  g_dinv[NN];          // rsqrt(deg+1)
__device__ int    g_cnt[NN];           // in-degree histogram (excl. self loop)
__device__ int    g_rowptr[NN];        // CSR row start
__device__ int    g_cursor[NN];        // scatter cursors
__device__ int    g_bsum[NB_SCAN];     // scan partials
__device__ int    g_csr_src[NE];       // CSR column (src) indices
__device__ __half g_Xl_h[NN * DH];     // RAW transformed features, fp16 (gather source)
__device__ float  g_agg[NN * DH];      // H activations (layer-1 output, fp32)

// ---------------- CSR build ----------------
__global__ void k_zero_cnt(int n) {
    int i = blockIdx.x * blockDim.x + threadIdx.x;
    if (i < n) g_cnt[i] = 0;
}

__global__ void k_hist(const int* __restrict__ dst, int nE) {
    int e = blockIdx.x * blockDim.x + threadIdx.x;
    if (e < nE) atomicAdd(&g_cnt[dst[e]], 1);
}

__global__ __launch_bounds__(1024) void k_scan1(int n) {
    __shared__ int s[1024];
    int i = blockIdx.x * 1024 + threadIdx.x;
    int v = (i < n) ? g_cnt[i] : 0;
    s[threadIdx.x] = v;
    __syncthreads();
    for (int off = 1; off < 1024; off <<= 1) {
        int t = (threadIdx.x >= off) ? s[threadIdx.x - off] : 0;
        __syncthreads();
        s[threadIdx.x] += t;
        __syncthreads();
    }
    if (i < n) g_rowptr[i] = s[threadIdx.x] - v;       // exclusive
    if (threadIdx.x == 1023) g_bsum[blockIdx.x] = s[1023];
}

__global__ __launch_bounds__(128) void k_scan2(int nb) {
    __shared__ int s[128];
    int v = (threadIdx.x < nb) ? g_bsum[threadIdx.x] : 0;
    s[threadIdx.x] = v;
    __syncthreads();
    for (int off = 1; off < 128; off <<= 1) {
        int t = (threadIdx.x >= off) ? s[threadIdx.x - off] : 0;
        __syncthreads();
        s[threadIdx.x] += t;
        __syncthreads();
    }
    if (threadIdx.x < nb) g_bsum[threadIdx.x] = s[threadIdx.x] - v;  // exclusive
}

__global__ void k_scan3(int n) {
    int i = blockIdx.x * blockDim.x + threadIdx.x;
    if (i >= n) return;
    int rp = g_rowptr[i] + g_bsum[i >> 10];
    g_rowptr[i] = rp;
    g_cursor[i] = rp;
    g_dinv[i] = rsqrtf((float)g_cnt[i] + 1.0f);
}

__global__ void k_scatter(const int* __restrict__ src, const int* __restrict__ dst, int nE) {
    int e = blockIdx.x * blockDim.x + threadIdx.x;
    if (e >= nE) return;
    int d = dst[e];
    int pos = atomicAdd(&g_cursor[d], 1);
    g_csr_src[pos] = src[e];
}

// ---------------- double-buffered register-blocked GEMM ----------------
// g_Xl_h[i,:] = fp16( X[i,:] @ W )   (fp32 accumulate)
// Tile: 128 nodes x 64 cols per block (256 threads), 4x8 per thread, TK=16.
// One __syncthreads per K-tile; global loads for tile t+1 prefetched into
// registers while computing tile t.
template <int K>
__global__ __launch_bounds__(256) void k_gemm(const float* __restrict__ X,
                                              const float* __restrict__ W,
                                              int n) {
    constexpr int NT = K / 16;
    __shared__ float sX[2][128 * 20];   // [row][k] stride 20 (16B-aligned rows)
    __shared__ float sW[2][16 * 64];

    const int node0 = blockIdx.x * 128;
    const int tid = threadIdx.x;
    const int tr = tid >> 3;            // 0..31
    const int tc = tid & 7;             // 0..7

    // loader coordinates
    const int xr0 = tid >> 2;                 // row for X-load part 0 (0..63)
    const int xr1 = (tid + 256) >> 2;         // row for part 1 (64..127)
    const int xc  = (tid & 3) * 4;            // k sub-offset
    const int wk  = tid >> 4;                 // 0..15
    const int wc  = (tid & 15) * 4;

    const bool xv0 = (node0 + xr0) < n;
    const bool xv1 = (node0 + xr1) < n;
    const float* Xr0 = X + (size_t)(node0 + xr0) * K + xc;
    const float* Xr1 = X + (size_t)(node0 + xr1) * K + xc;

    // ---- load tile 0 straight into smem ----
    {
        float4 a = xv0 ? *reinterpret_cast<const float4*>(Xr0)
                       : make_float4(0.f, 0.f, 0.f, 0.f);
        float4 b = xv1 ? *reinterpret_cast<const float4*>(Xr1)
                       : make_float4(0.f, 0.f, 0.f, 0.f);
        *reinterpret_cast<float4*>(&sX[0][xr0 * 20 + xc]) = a;
        *reinterpret_cast<float4*>(&sX[0][xr1 * 20 + xc]) = b;
        *reinterpret_cast<float4*>(&sW[0][wk * 64 + wc]) =
            *reinterpret_cast<const float4*>(W + (size_t)wk * 64 + wc);
    }
    __syncthreads();

    float acc[4][8];
#pragma unroll
    for (int i = 0; i < 4; i++)
#pragma unroll
        for (int j = 0; j < 8; j++) acc[i][j] = 0.f;

    for (int t = 0; t < NT; t++) {
        const int buf = t & 1;
        float4 pa, pb, pw;
        if (t + 1 < NT) {
            const int k0 = (t + 1) * 16;
            pa = xv0 ? *reinterpret_cast<const float4*>(Xr0 + k0)
                     : make_float4(0.f, 0.f, 0.f, 0.f);
            pb = xv1 ? *reinterpret_cast<const float4*>(Xr1 + k0)
                     : make_float4(0.f, 0.f, 0.f, 0.f);
            pw = *reinterpret_cast<const float4*>(W + (size_t)(k0 + wk) * 64 + wc);
        }

        // ---- compute on buf: k vectorized by 4 ----
#pragma unroll
        for (int k4 = 0; k4 < 4; k4++) {
            float4 xv[4];
#pragma unroll
            for (int i = 0; i < 4; i++)
                xv[i] = *reinterpret_cast<const float4*>(&sX[buf][(tr * 4 + i) * 20 + k4 * 4]);
#pragma unroll
            for (int kk = 0; kk < 4; kk++) {
                const float* wrow = &sW[buf][(k4 * 4 + kk) * 64 + tc * 8];
                float4 w0 = *reinterpret_cast<const float4*>(wrow);
                float4 w1 = *reinterpret_cast<const float4*>(wrow + 4);
#pragma unroll
                for (int i = 0; i < 4; i++) {
                    float x = (kk == 0) ? xv[i].x : (kk == 1) ? xv[i].y
                            : (kk == 2) ? xv[i].z : xv[i].w;
                    acc[i][0] = fmaf(x, w0.x, acc[i][0]);
                    acc[i][1] = fmaf(x, w0.y, acc[i][1]);
                    acc[i][2] = fmaf(x, w0.z, acc[i][2]);
                    acc[i][3] = fmaf(x, w0.w, acc[i][3]);
                    acc[i][4] = fmaf(x, w1.x, acc[i][4]);
                    acc[i][5] = fmaf(x, w1.y, acc[i][5]);
                    acc[i][6] = fmaf(x, w1.z, acc[i][6]);
                    acc[i][7] = fmaf(x, w1.w, acc[i][7]);
                }
            }
        }

        if (t + 1 < NT) {
            const int nbuf = buf ^ 1;
            *reinterpret_cast<float4*>(&sX[nbuf][xr0 * 20 + xc]) = pa;
            *reinterpret_cast<float4*>(&sX[nbuf][xr1 * 20 + xc]) = pb;
            *reinterpret_cast<float4*>(&sW[nbuf][wk * 64 + wc]) = pw;
            __syncthreads();
        }
    }

    // ---- epilogue: fp16 store (8 halves = 16B per thread-row) ----
#pragma unroll
    for (int i = 0; i < 4; i++) {
        int node = node0 + tr * 4 + i;
        if (node < n) {
            __half2 h[4];
            h[0] = __floats2half2_rn(acc[i][0], acc[i][1]);
            h[1] = __floats2half2_rn(acc[i][2], acc[i][3]);
            h[2] = __floats2half2_rn(acc[i][4], acc[i][5]);
            h[3] = __floats2half2_rn(acc[i][6], acc[i][7]);
            *reinterpret_cast<uint4*>(g_Xl_h + (size_t)node * DH + tc * 8) =
                *reinterpret_cast<uint4*>(h);
        }
    }
}

// ---------------- CSR gather aggregation (fp16 source, fp32 accumulate) ----------------
// One warp per node; lane owns 2 columns (one half2, 4B coalesced loads).
//   acc = dinv[node]*Xl[node] + sum_{s in row} dinv[s]*Xl[s]
//   MODE 0: g_agg[node] = relu(acc * dinv + b)      (layer 1 -> H, fp32)
//   MODE 1: out[node]   = acc * dinv + b            (layer 2 -> output)
template <int MODE>
__global__ __launch_bounds__(256) void k_gather(const float* __restrict__ bias,
                                                float* __restrict__ outbuf, int n) {
    int gw = (blockIdx.x * blockDim.x + threadIdx.x) >> 5;
    if (gw >= n) return;
    const int lane = threadIdx.x & 31;
    const int start = g_rowptr[gw];
    const int cnt   = g_cnt[gw];
    const float dvd = g_dinv[gw];
    const __half2* base = reinterpret_cast<const __half2*>(g_Xl_h);

    float2 acc;
    {
        float2 sf = __half22float2(base[(size_t)gw * 32 + lane]);
        acc.x = sf.x * dvd;
        acc.y = sf.y * dvd;
    }

    int j0 = 0;
    for (; j0 + 32 <= cnt; j0 += 32) {              // full-warp batches
        int   myidx = g_csr_src[start + j0 + lane];
        float myd   = g_dinv[myidx];
#pragma unroll
        for (int t = 0; t < 32; t++) {
            int   s = __shfl_sync(0xffffffffu, myidx, t);
            float d = __shfl_sync(0xffffffffu, myd,   t);
            float2 v = __half22float2(base[(size_t)s * 32 + lane]);
            acc.x = fmaf(d, v.x, acc.x);
            acc.y = fmaf(d, v.y, acc.y);
        }
    }
    int rem = cnt - j0;
    if (rem > 0) {
        int   myidx = 0; float myd = 0.f;
        if (lane < rem) {
            myidx = g_csr_src[start + j0 + lane];
            myd   = g_dinv[myidx];
        }
        for (int t = 0; t < rem; t++) {
            int   s = __shfl_sync(0xffffffffu, myidx, t);
            float d = __shfl_sync(0xffffffffu, myd,   t);
            float2 v = __half22float2(base[(size_t)s * 32 + lane]);
            acc.x = fmaf(d, v.x, acc.x);
            acc.y = fmaf(d, v.y, acc.y);
        }
    }

    float2 bb = *reinterpret_cast<const float2*>(bias + lane * 2);
    float2 o;
    o.x = fmaf(acc.x, dvd, bb.x);
    o.y = fmaf(acc.y, dvd, bb.y);
    if (MODE == 0) { o.x = fmaxf(o.x, 0.f); o.y = fmaxf(o.y, 0.f); }
    float* dstp = (MODE == 0) ? (g_agg + (size_t)gw * DH + lane * 2)
                              : (outbuf + (size_t)gw * DH + lane * 2);
    *reinterpret_cast<float2*>(dstp) = o;
}

// ---------------- host launch ----------------
extern "C" void kernel_launch(void* const* d_in, const int* in_sizes, int n_in,
                              void* d_out, int out_size) {
    const int*   E  = nullptr;
    const float* X  = nullptr;
    const float* W1 = nullptr;
    const float* b1 = nullptr;
    const float* W2 = nullptr;
    const float* b2 = nullptr;
    long nE_total = 0;
    for (int i = 0; i < n_in; i++) {
        long sz = in_sizes[i];
        if (sz == 2L * NE)           { E = (const int*)d_in[i]; nE_total = sz / 2; }
        else if (sz == (long)NN * DIN) X  = (const float*)d_in[i];
        else if (sz == DIN * DH)       W1 = (const float*)d_in[i];
        else if (sz == DH * DH)        W2 = (const float*)d_in[i];
        else if (sz == DH)             { if (!b1) b1 = (const float*)d_in[i];
                                         else     b2 = (const float*)d_in[i]; }
    }
    const int n  = NN;
    const int nE = (int)nE_total;
    const int* src = E;          // E[0]
    const int* dst = E + nE;     // E[1]
    float* out = (float*)d_out;

    void* aptr = nullptr;
    cudaGetSymbolAddress(&aptr, g_agg);
    const float* Hdev = (const float*)aptr;

    static cudaStream_t s1 = nullptr;
    static cudaEvent_t  eFork = nullptr, eJoin = nullptr;
    if (s1 == nullptr) {
        cudaStreamCreateWithFlags(&s1, cudaStreamNonBlocking);
        cudaEventCreateWithFlags(&eFork, cudaEventDisableTiming);
        cudaEventCreateWithFlags(&eJoin, cudaEventDisableTiming);
    }

    const int T = 256;
    dim3 blkNode((n + T - 1) / T);
    dim3 blkEdge((nE + T - 1) / T);
    dim3 blkGemm((n + 127) / 128);
    dim3 blkWarp(((long)n * 32 + T - 1) / T);

    // ---- fork: CSR build (+dinv) on s1, concurrent with GEMM1 ----
    cudaEventRecord(eFork, 0);
    cudaStreamWaitEvent(s1, eFork, 0);

    k_zero_cnt<<<blkNode, T, 0, s1>>>(n);
    k_hist<<<blkEdge, T, 0, s1>>>(dst, nE);
    k_scan1<<<NB_SCAN, 1024, 0, s1>>>(n);
    k_scan2<<<1, 128, 0, s1>>>(NB_SCAN);
    k_scan3<<<blkNode, T, 0, s1>>>(n);
    k_scatter<<<blkEdge, T, 0, s1>>>(src, dst, nE);
    cudaEventRecord(eJoin, s1);

    // ---- main chain ----
    k_gemm<DIN><<<blkGemm, T>>>(X, W1, n);
    cudaStreamWaitEvent(0, eJoin, 0);

    k_gather<0><<<blkWarp, T>>>(b1, nullptr, n);
    k_gemm<DH><<<blkGemm, T>>>(Hdev, W2, n);
    k_gather<1><<<blkWarp, T>>>(b2, out, n);
}

// round 7
// speedup vs baseline: 2.9083x; 1.3732x over previous
#include <cuda_runtime.h>
#include <cuda_fp16.h>
#include <mma.h>
#include <cstdint>

using namespace nvcuda;

// Problem constants (fixed shapes per reference)
#define NN 100000
#define NE 1600000
#define DIN 128
#define DH 64
#define NB_SCAN ((NN + 1023) / 1024)   // 98

// ---------------- scratch (no allocations allowed) ----------------
__device__ float  g_dinv[NN];
__device__ int    g_cnt[NN];
__device__ int    g_rowptr[NN];
__device__ int    g_cursor[NN];
__device__ int    g_bsum[NB_SCAN];
__device__ int    g_csr_src[NE];
__device__ __half g_Xh [NN * DIN];     // X converted to fp16
__device__ __half g_W1h[DIN * DH];
__device__ __half g_W2h[DH * DH];
__device__ __half g_Xl_h[NN * DH];     // transformed features (gather source, fp16)
__device__ __half g_H_h [NN * DH];     // layer-1 activations (fp16)

// ---------------- CSR build ----------------
__global__ void k_zero_cnt(int n) {
    int i = blockIdx.x * blockDim.x + threadIdx.x;
    if (i < n) g_cnt[i] = 0;
}

__global__ void k_hist(const int* __restrict__ dst, int nE) {
    int e = blockIdx.x * blockDim.x + threadIdx.x;
    if (e < nE) atomicAdd(&g_cnt[dst[e]], 1);
}

__global__ __launch_bounds__(1024) void k_scan1(int n) {
    __shared__ int s[1024];
    int i = blockIdx.x * 1024 + threadIdx.x;
    int v = (i < n) ? g_cnt[i] : 0;
    s[threadIdx.x] = v;
    __syncthreads();
    for (int off = 1; off < 1024; off <<= 1) {
        int t = (threadIdx.x >= off) ? s[threadIdx.x - off] : 0;
        __syncthreads();
        s[threadIdx.x] += t;
        __syncthreads();
    }
    if (i < n) g_rowptr[i] = s[threadIdx.x] - v;       // exclusive
    if (threadIdx.x == 1023) g_bsum[blockIdx.x] = s[1023];
}

__global__ __launch_bounds__(128) void k_scan2(int nb) {
    __shared__ int s[128];
    int v = (threadIdx.x < nb) ? g_bsum[threadIdx.x] : 0;
    s[threadIdx.x] = v;
    __syncthreads();
    for (int off = 1; off < 128; off <<= 1) {
        int t = (threadIdx.x >= off) ? s[threadIdx.x - off] : 0;
        __syncthreads();
        s[threadIdx.x] += t;
        __syncthreads();
    }
    if (threadIdx.x < nb) g_bsum[threadIdx.x] = s[threadIdx.x] - v;  // exclusive
}

__global__ void k_scan3(int n) {
    int i = blockIdx.x * blockDim.x + threadIdx.x;
    if (i >= n) return;
    int rp = g_rowptr[i] + g_bsum[i >> 10];
    g_rowptr[i] = rp;
    g_cursor[i] = rp;
    g_dinv[i] = rsqrtf((float)g_cnt[i] + 1.0f);
}

__global__ void k_scatter(const int* __restrict__ src, const int* __restrict__ dst, int nE) {
    int e = blockIdx.x * blockDim.x + threadIdx.x;
    if (e >= nE) return;
    int d = dst[e];
    int pos = atomicAdd(&g_cursor[d], 1);
    g_csr_src[pos] = src[e];
}

// ---------------- conversions ----------------
__global__ void k_conv_X(const float* __restrict__ X, long n4) {
    long i = (long)blockIdx.x * blockDim.x + threadIdx.x;
    if (i >= n4) return;
    float4 v = reinterpret_cast<const float4*>(X)[i];
    __half2 h[2];
    h[0] = __floats2half2_rn(v.x, v.y);
    h[1] = __floats2half2_rn(v.z, v.w);
    reinterpret_cast<uint2*>(g_Xh)[i] = *reinterpret_cast<uint2*>(h);
}

__global__ void k_conv_W(const float* __restrict__ W1, const float* __restrict__ W2) {
    int i = blockIdx.x * blockDim.x + threadIdx.x;
    if (i < DIN * DH) g_W1h[i] = __float2half_rn(W1[i]);
    if (i < DH * DH)  g_W2h[i] = __float2half_rn(W2[i]);
}

// ---------------- tensor-core GEMM: out = fp16( Xh @ Wh ), fp32 accum ----------------
// Block: 128 rows x 64 cols, 256 threads = 8 warps. Warp w owns rows [16w,16w+16),
// 4 col-tiles of 16. K processed in KT=64 chunks held in padded smem.
template <int K>
__global__ __launch_bounds__(256) void k_gemm_tc(const __half* __restrict__ Xh,
                                                 const __half* __restrict__ Wh,
                                                 __half* __restrict__ outh, int n) {
    constexpr int KT = 64;
    constexpr int NT = K / KT;
    __shared__ __half sA[128][72];          // 18432 B (pad 8 -> LDSM conflict-free)
    __shared__ __half sB[64][72];           //  9216 B
    __shared__ float  sStage[8][16 * 20];   // 10240 B per-warp fp32 staging

    const int tid = threadIdx.x;
    const int wid = tid >> 5;
    const int lane = tid & 31;
    const int node0 = blockIdx.x * 128;

    // loader coords
    const int ar = tid >> 1;          // 0..127
    const int as = (tid & 1) * 32;    // half-offset in KT
    const int br = tid >> 2;          // 0..63
    const int bs = (tid & 3) * 16;

    wmma::fragment<wmma::accumulator, 16, 16, 16, float> facc[4];
#pragma unroll
    for (int c = 0; c < 4; c++) wmma::fill_fragment(facc[c], 0.0f);

    for (int kt = 0; kt < NT; kt++) {
        // load A tile: 128 rows x 64 halves (each thread: 32 halves = 4x uint4)
        {
            const int node = node0 + ar;
            if (node < n) {
                const uint4* srcp = reinterpret_cast<const uint4*>(
                    Xh + (size_t)node * K + kt * KT + as);
                uint4* dstp = reinterpret_cast<uint4*>(&sA[ar][as]);
#pragma unroll
                for (int u = 0; u < 4; u++) dstp[u] = srcp[u];
            } else {
                uint4 z = make_uint4(0, 0, 0, 0);
                uint4* dstp = reinterpret_cast<uint4*>(&sA[ar][as]);
#pragma unroll
                for (int u = 0; u < 4; u++) dstp[u] = z;
            }
        }
        // load B tile: 64 rows x 64 halves (each thread: 16 halves = 2x uint4)
        {
            const uint4* srcp = reinterpret_cast<const uint4*>(
                Wh + (size_t)(kt * KT + br) * DH + bs);
            uint4* dstp = reinterpret_cast<uint4*>(&sB[br][bs]);
            dstp[0] = srcp[0];
            dstp[1] = srcp[1];
        }
        __syncthreads();

#pragma unroll
        for (int k8 = 0; k8 < KT / 16; k8++) {
            wmma::fragment<wmma::matrix_a, 16, 16, 16, __half, wmma::row_major> fa;
            wmma::load_matrix_sync(fa, &sA[wid * 16][k8 * 16], 72);
#pragma unroll
            for (int c = 0; c < 4; c++) {
                wmma::fragment<wmma::matrix_b, 16, 16, 16, __half, wmma::row_major> fb;
                wmma::load_matrix_sync(fb, &sB[k8 * 16][c * 16], 72);
                wmma::mma_sync(facc[c], fa, fb, facc[c]);
            }
        }
        if (kt + 1 < NT) __syncthreads();
    }

    // epilogue: stage fp32 per warp, convert to fp16, store 16B per lane
    const int erow = lane >> 1;          // 0..15
    const int eseg = (lane & 1) * 8;     // 0 or 8
#pragma unroll
    for (int c = 0; c < 4; c++) {
        wmma::store_matrix_sync(&sStage[wid][0], facc[c], 20, wmma::mem_row_major);
        __syncwarp();
        const int node = node0 + wid * 16 + erow;
        if (node < n) {
            const float* sp = &sStage[wid][erow * 20 + eseg];
            __half2 h[4];
            h[0] = __floats2half2_rn(sp[0], sp[1]);
            h[1] = __floats2half2_rn(sp[2], sp[3]);
            h[2] = __floats2half2_rn(sp[4], sp[5]);
            h[3] = __floats2half2_rn(sp[6], sp[7]);
            *reinterpret_cast<uint4*>(outh + (size_t)node * DH + c * 16 + eseg) =
                *reinterpret_cast<uint4*>(h);
        }
        __syncwarp();
    }
}

// ---------------- CSR gather aggregation (fp16 source, fp32 accumulate) ----------------
// One warp per node; lane owns 2 columns (one half2 load per row).
//   MODE 0: g_H_h[node] = fp16(relu(acc * dinv + b))
//   MODE 1: out[node]   = acc * dinv + b            (fp32)
template <int MODE>
__global__ __launch_bounds__(256) void k_gather(const float* __restrict__ bias,
                                                float* __restrict__ outbuf, int n) {
    int gw = (blockIdx.x * blockDim.x + threadIdx.x) >> 5;
    if (gw >= n) return;
    const int lane = threadIdx.x & 31;
    const int start = g_rowptr[gw];
    const int cnt   = g_cnt[gw];
    const float dvd = g_dinv[gw];
    const __half2* base = reinterpret_cast<const __half2*>(g_Xl_h);

    float2 acc;
    {
        float2 sf = __half22float2(base[(size_t)gw * 32 + lane]);
        acc.x = sf.x * dvd;
        acc.y = sf.y * dvd;
    }

    int j0 = 0;
    for (; j0 + 32 <= cnt; j0 += 32) {
        int   myidx = g_csr_src[start + j0 + lane];
        float myd   = g_dinv[myidx];
#pragma unroll
        for (int t = 0; t < 32; t++) {
            int   s = __shfl_sync(0xffffffffu, myidx, t);
            float d = __shfl_sync(0xffffffffu, myd,   t);
            float2 v = __half22float2(base[(size_t)s * 32 + lane]);
            acc.x = fmaf(d, v.x, acc.x);
            acc.y = fmaf(d, v.y, acc.y);
        }
    }
    int rem = cnt - j0;
    if (rem > 0) {
        int   myidx = 0; float myd = 0.f;
        if (lane < rem) {
            myidx = g_csr_src[start + j0 + lane];
            myd   = g_dinv[myidx];
        }
        for (int t = 0; t < rem; t++) {
            int   s = __shfl_sync(0xffffffffu, myidx, t);
            float d = __shfl_sync(0xffffffffu, myd,   t);
            float2 v = __half22float2(base[(size_t)s * 32 + lane]);
            acc.x = fmaf(d, v.x, acc.x);
            acc.y = fmaf(d, v.y, acc.y);
        }
    }

    float2 bb = *reinterpret_cast<const float2*>(bias + lane * 2);
    float2 o;
    o.x = fmaf(acc.x, dvd, bb.x);
    o.y = fmaf(acc.y, dvd, bb.y);
    if (MODE == 0) {
        o.x = fmaxf(o.x, 0.f); o.y = fmaxf(o.y, 0.f);
        reinterpret_cast<__half2*>(g_H_h)[(size_t)gw * 32 + lane] =
            __floats2half2_rn(o.x, o.y);
    } else {
        *reinterpret_cast<float2*>(outbuf + (size_t)gw * DH + lane * 2) = o;
    }
}

// ---------------- host launch ----------------
extern "C" void kernel_launch(void* const* d_in, const int* in_sizes, int n_in,
                              void* d_out, int out_size) {
    const int*   E  = nullptr;
    const float* X  = nullptr;
    const float* W1 = nullptr;
    const float* b1 = nullptr;
    const float* W2 = nullptr;
    const float* b2 = nullptr;
    long nE_total = 0;
    for (int i = 0; i < n_in; i++) {
        long sz = in_sizes[i];
        if (sz == 2L * NE)           { E = (const int*)d_in[i]; nE_total = sz / 2; }
        else if (sz == (long)NN * DIN) X  = (const float*)d_in[i];
        else if (sz == DIN * DH)       W1 = (const float*)d_in[i];
        else if (sz == DH * DH)        W2 = (const float*)d_in[i];
        else if (sz == DH)             { if (!b1) b1 = (const float*)d_in[i];
                                         else     b2 = (const float*)d_in[i]; }
    }
    const int n  = NN;
    const int nE = (int)nE_total;
    const int* src = E;          // E[0]
    const int* dst = E + nE;     // E[1]
    float* out = (float*)d_out;

    // device symbol addresses (cannot name device symbols from host as args)
    void *pXh = nullptr, *pW1h = nullptr, *pW2h = nullptr, *pXlh = nullptr, *pHh = nullptr;
    cudaGetSymbolAddress(&pXh,  g_Xh);
    cudaGetSymbolAddress(&pW1h, g_W1h);
    cudaGetSymbolAddress(&pW2h, g_W2h);
    cudaGetSymbolAddress(&pXlh, g_Xl_h);
    cudaGetSymbolAddress(&pHh,  g_H_h);

    static cudaStream_t s1 = nullptr;
    static cudaEvent_t  eFork = nullptr, eJoin = nullptr;
    if (s1 == nullptr) {
        cudaStreamCreateWithFlags(&s1, cudaStreamNonBlocking);
        cudaEventCreateWithFlags(&eFork, cudaEventDisableTiming);
        cudaEventCreateWithFlags(&eJoin, cudaEventDisableTiming);
    }

    const int T = 256;
    dim3 blkNode((n + T - 1) / T);
    dim3 blkEdge((nE + T - 1) / T);
    dim3 blkGemm((n + 127) / 128);
    dim3 blkWarp(((long)n * 32 + T - 1) / T);
    long nX4 = (long)n * DIN / 4;
    dim3 blkConv((nX4 + T - 1) / T);

    // ---- fork: CSR build (+dinv) on s1, concurrent with conversions + GEMM1 ----
    cudaEventRecord(eFork, 0);
    cudaStreamWaitEvent(s1, eFork, 0);

    k_zero_cnt<<<blkNode, T, 0, s1>>>(n);
    k_hist<<<blkEdge, T, 0, s1>>>(dst, nE);
    k_scan1<<<NB_SCAN, 1024, 0, s1>>>(n);
    k_scan2<<<1, 128, 0, s1>>>(NB_SCAN);
    k_scan3<<<blkNode, T, 0, s1>>>(n);
    k_scatter<<<blkEdge, T, 0, s1>>>(src, dst, nE);
    cudaEventRecord(eJoin, s1);

    // ---- main chain ----
    k_conv_X<<<blkConv, T>>>(X, nX4);
    k_conv_W<<<(DIN * DH + T - 1) / T, T>>>(W1, W2);
    k_gemm_tc<DIN><<<blkGemm, T>>>((const __half*)pXh, (const __half*)pW1h,
                                   (__half*)pXlh, n);
    cudaStreamWaitEvent(0, eJoin, 0);

    k_gather<0><<<blkWarp, T>>>(b1, nullptr, n);
    k_gemm_tc<DH><<<blkGemm, T>>>((const __half*)pHh, (const __half*)pW2h,
                                  (__half*)pXlh, n);
    k_gather<1><<<blkWarp, T>>>(b2, out, n);
}